// round 12
// baseline (speedup 1.0000x reference)
#include <cuda_runtime.h>
#include <cuda_fp16.h>
#include <cstdint>
#include <math.h>

#define B_   4
#define H_   64
#define W_   128
#define DM_  256
#define NH_  8
#define NPIX (B_*H_*W_)      // 32768
#define NOAP 256             // padded offA width (128 off + 64 attn + 64 pad)
#define KDIM 256
#define NDIM 256

// BK=64 tile, staged as two 32-K halves. Dynamic smem.
#define AS_STRIDE 36
#define BS_STRIDE 136
#define AS_BUF (128*AS_STRIDE)   // 4608 words per buffer (128 rows x 32 half2 + pad)
#define BS_BUF (32*BS_STRIDE)    // 4352 words per buffer (32 k-pairs x 128 n + pad)
#define SMEM_WORDS (2*AS_BUF + 2*BS_BUF)
#define SMEM_BYTES (SMEM_WORDS*4)   // 71680

// ------------------------- scratch (device globals; no allocation) -------------------------
__device__ __align__(256) __half g_sf0h [NPIX*DM_];
__device__ __align__(256) __half g_sf1h [NPIX*DM_];
__device__ __align__(256) __half g_feath[NPIX*DM_];
__device__ __align__(256) float  g_offA [NPIX*NOAP];
__device__ __align__(256) float  g_Weff [DM_*NOAP];
__device__ __align__(256) float  g_beff [NOAP];

// --------- Weff = Wq @ [Wo | Wa | 0] (blocks 0..255), beff = bq@Wcat + [bo|ba|0] (block 256)
__global__ void wbeff_kernel(const float* __restrict__ Wq, const float* __restrict__ Wo,
                             const float* __restrict__ Wa, const float* __restrict__ bq,
                             const float* __restrict__ bo, const float* __restrict__ ba)
{
    __shared__ float wq[DM_];
    const int r = blockIdx.x;
    const int c = threadIdx.x;
    const bool isBias = (r == DM_);
    wq[c] = isBias ? bq[c] : Wq[r * DM_ + c];
    __syncthreads();
    float acc = 0.f;
    if (c < 128) {
        for (int k = 0; k < DM_; k++) acc += wq[k] * Wo[k * 128 + c];
        if (isBias) acc += bo[c];
    } else if (c < 192) {
        const int cc = c - 128;
        for (int k = 0; k < DM_; k++) acc += wq[k] * Wa[k * 64 + cc];
        if (isBias) acc += ba[cc];
    }
    if (isBias) g_beff[c] = (c < 192) ? acc : 0.f;
    else        g_Weff[r * NOAP + c] = (c < 192) ? acc : 0.f;
}

// ------------------------- FP16 tensor-core GEMM core --------------------------------------
// CTA tile 128x128, BK=64 K-tiles staged as two 32-K halves (register footprint of BK=32,
// but only ONE __syncthreads per 64-K). 8 warps (4m x 2n), warp tile 32x64 = 2x8 m16n8k16.
// Double-buffered dynamic smem; conflict-free fragment LDS; 2 CTAs/SM.

__device__ __forceinline__ unsigned pack2(float x, float y) {
    __half2 h = __floats2half2_rn(x, y);
    return *reinterpret_cast<unsigned*>(&h);
}

template<typename T>
__device__ __forceinline__ uint2 loadA4(const T* p);
template<>
__device__ __forceinline__ uint2 loadA4<float>(const float* p) {
    float4 v = *(const float4*)p;
    return make_uint2(pack2(v.x, v.y), pack2(v.z, v.w));
}
template<>
__device__ __forceinline__ uint2 loadA4<__half>(const __half* p) {
    return *(const uint2*)p;
}

template<typename T>
__device__ __forceinline__ void storeC2(T* C, size_t idx, float v0, float v1);
template<>
__device__ __forceinline__ void storeC2<float>(float* C, size_t idx, float v0, float v1) {
    *(float2*)(C + idx) = make_float2(v0, v1);
}
template<>
__device__ __forceinline__ void storeC2<__half>(__half* C, size_t idx, float v0, float v1) {
    *(unsigned*)(C + idx) = pack2(v0, v1);
}

__device__ __forceinline__ void mma_f16(float c[4], const unsigned a[4], const unsigned b[2]) {
    asm volatile(
        "mma.sync.aligned.m16n8k16.row.col.f32.f16.f16.f32 "
        "{%0,%1,%2,%3}, {%4,%5,%6,%7}, {%8,%9}, {%0,%1,%2,%3};"
        : "+f"(c[0]), "+f"(c[1]), "+f"(c[2]), "+f"(c[3])
        : "r"(a[0]), "r"(a[1]), "r"(a[2]), "r"(a[3]), "r"(b[0]), "r"(b[1]));
}

template<typename TIN, typename TOUT>
__device__ __forceinline__
void gemm_core(const TIN* __restrict__ A, const float* __restrict__ Bm,
               const float* __restrict__ bias, TOUT* __restrict__ C,
               unsigned* __restrict__ sAs, unsigned* __restrict__ sBs)
{
    const int tid  = threadIdx.x;
    const int lane = tid & 31;
    const int wid  = tid >> 5;
    const int g    = lane >> 2;
    const int tg   = lane & 3;
    const int warpRow = (wid & 3) * 32;
    const int warpCol = (wid >> 2) * 64;
    const int rowBase = blockIdx.y * 128;
    const int colBase = blockIdx.x * 128;

    const int am  = tid >> 3;          // A row 0..31 (+32*i)
    const int akc = (tid & 7) * 4;     // A k element offset within 32-chunk
    const int ac2 = (tid & 7) * 2;     // A half2 slot within 16-col half
    const int bp  = tid >> 5;          // B k-pair 0..7 (+8) within 16-pair half
    const int bnc = (tid & 31) * 4;    // B n col chunk

    const TIN*   Ap = A + (size_t)rowBase * KDIM;
    const float* Bp = Bm + colBase;

    uint2    ra[4];
    unsigned rbp[8];

// ck = 32-K chunk index (0..7)
#define GLOAD(ck)                                                                         \
    {                                                                                     \
        _Pragma("unroll")                                                                 \
        for (int i = 0; i < 4; i++)                                                       \
            ra[i] = loadA4<TIN>(Ap + (size_t)(am + 32 * i) * KDIM + (ck) * 32 + akc);     \
        {                                                                                 \
            float4 b0 = *(const float4*)(Bp + (size_t)((ck) * 32 + 2 * bp    ) * NDIM + bnc); \
            float4 b1 = *(const float4*)(Bp + (size_t)((ck) * 32 + 2 * bp + 1) * NDIM + bnc); \
            rbp[0] = pack2(b0.x, b1.x); rbp[1] = pack2(b0.y, b1.y);                       \
            rbp[2] = pack2(b0.z, b1.z); rbp[3] = pack2(b0.w, b1.w);                       \
            float4 b2 = *(const float4*)(Bp + (size_t)((ck) * 32 + 2 * bp + 16) * NDIM + bnc); \
            float4 b3 = *(const float4*)(Bp + (size_t)((ck) * 32 + 2 * bp + 17) * NDIM + bnc); \
            rbp[4] = pack2(b2.x, b3.x); rbp[5] = pack2(b2.y, b3.y);                       \
            rbp[6] = pack2(b2.z, b3.z); rbp[7] = pack2(b2.w, b3.w);                       \
        }                                                                                 \
    }

// write registers into half hh (0/1) of buffer buf
#define SSTORE(buf, hh)                                                                   \
    {                                                                                     \
        _Pragma("unroll")                                                                 \
        for (int i = 0; i < 4; i++)                                                       \
            *(uint2*)(&sAs[(buf)*AS_BUF + (am + 32 * i)*AS_STRIDE + (hh)*16 + ac2]) = ra[i]; \
        *(uint4*)(&sBs[(buf)*BS_BUF + ((hh)*16 + bp)*BS_STRIDE + bnc])                    \
            = make_uint4(rbp[0], rbp[1], rbp[2], rbp[3]);                                 \
        *(uint4*)(&sBs[(buf)*BS_BUF + ((hh)*16 + bp + 8)*BS_STRIDE + bnc])                \
            = make_uint4(rbp[4], rbp[5], rbp[6], rbp[7]);                                 \
    }

// one mma sub-stage: s in 0..3, kc0 = s*8 half2-cols
#define MMA_STAGE(As, Bs, s)                                                              \
    {                                                                                     \
        const int kc0 = (s) * 8;                                                         \
        unsigned af[2][4];                                                                \
        _Pragma("unroll")                                                                 \
        for (int mt = 0; mt < 2; mt++) {                                                  \
            const int r0 = warpRow + mt * 16 + g;                                         \
            af[mt][0] = (As)[r0 * AS_STRIDE + kc0 + tg];                                  \
            af[mt][1] = (As)[(r0 + 8) * AS_STRIDE + kc0 + tg];                            \
            af[mt][2] = (As)[r0 * AS_STRIDE + kc0 + 4 + tg];                              \
            af[mt][3] = (As)[(r0 + 8) * AS_STRIDE + kc0 + 4 + tg];                        \
        }                                                                                 \
        unsigned bf[8][2];                                                                \
        _Pragma("unroll")                                                                 \
        for (int nt = 0; nt < 8; nt++) {                                                  \
            const int c0 = warpCol + nt * 8 + g;                                          \
            bf[nt][0] = (Bs)[(kc0 + tg) * BS_STRIDE + c0];                                \
            bf[nt][1] = (Bs)[(kc0 + 4 + tg) * BS_STRIDE + c0];                            \
        }                                                                                 \
        _Pragma("unroll")                                                                 \
        for (int mt = 0; mt < 2; mt++)                                                    \
            _Pragma("unroll")                                                             \
            for (int nt = 0; nt < 8; nt++)                                                \
                mma_f16(acc[mt][nt], af[mt], bf[nt]);                                     \
    }

    float acc[2][8][4];
#pragma unroll
    for (int mt = 0; mt < 2; mt++)
#pragma unroll
        for (int nt = 0; nt < 8; nt++)
#pragma unroll
            for (int j = 0; j < 4; j++) acc[mt][nt][j] = 0.f;

    // prologue: fill buffer 0 with 64-K tile 0 (two halves)
    GLOAD(0); SSTORE(0, 0);
    GLOAD(1); SSTORE(0, 1);
    __syncthreads();

    const int TILES = KDIM / 64;   // 4
#pragma unroll
    for (int kt = 0; kt < TILES; kt++) {
        const int cur = kt & 1;
        const int nxt = 1 - cur;
        const unsigned* As = sAs + cur * AS_BUF;
        const unsigned* Bs = sBs + cur * BS_BUF;

        if (kt < TILES - 1) GLOAD(2 * kt + 2);
        MMA_STAGE(As, Bs, 0);
        MMA_STAGE(As, Bs, 1);
        if (kt < TILES - 1) { SSTORE(nxt, 0); GLOAD(2 * kt + 3); }
        MMA_STAGE(As, Bs, 2);
        MMA_STAGE(As, Bs, 3);
        if (kt < TILES - 1) SSTORE(nxt, 1);
        __syncthreads();
    }

#pragma unroll
    for (int mt = 0; mt < 2; mt++) {
        const int row = rowBase + warpRow + mt * 16 + g;
#pragma unroll
        for (int nt = 0; nt < 8; nt++) {
            const int col = colBase + warpCol + nt * 8 + tg * 2;
            const float2 bv = *(const float2*)(bias + col);
            storeC2<TOUT>(C, (size_t)row * NDIM + col,
                          acc[mt][nt][0] + bv.x, acc[mt][nt][1] + bv.y);
            storeC2<TOUT>(C, (size_t)(row + 8) * NDIM + col,
                          acc[mt][nt][2] + bv.x, acc[mt][nt][3] + bv.y);
        }
    }
#undef GLOAD
#undef SSTORE
#undef MMA_STAGE
}

__global__ __launch_bounds__(256, 2)
void gemm_heads(const float* __restrict__ query, const float* __restrict__ Weff,
                const float* __restrict__ beff,  float* __restrict__ offA,
                const float* __restrict__ keys0, const float* __restrict__ keys1,
                const float* __restrict__ Wk,    const float* __restrict__ bk,
                __half* __restrict__ sf0h, __half* __restrict__ sf1h)
{
    extern __shared__ __align__(16) unsigned smem_dyn[];
    unsigned* sAs = smem_dyn;
    unsigned* sBs = smem_dyn + 2 * AS_BUF;
    if (blockIdx.z == 0)      gemm_core<float, float >(query, Weff, beff, offA, sAs, sBs);
    else if (blockIdx.z == 1) gemm_core<float, __half>(keys0, Wk, bk, sf0h, sAs, sBs);
    else                      gemm_core<float, __half>(keys1, Wk, bk, sf1h, sAs, sBs);
}

__global__ __launch_bounds__(256, 2)
void gemm_out(const __half* __restrict__ A, const float* __restrict__ Bm,
              const float* __restrict__ bias, float* __restrict__ C)
{
    extern __shared__ __align__(16) unsigned smem_dyn[];
    unsigned* sAs = smem_dyn;
    unsigned* sBs = smem_dyn + 2 * AS_BUF;
    gemm_core<__half, float>(A, Bm, bias, C, sAs, sBs);
}

// ------------------------- deformable sampling: two-phase ----------------------------------
// Block = 4 pixels. Phase 1 (256 thr = 4px x 8h x 8pt): softmax weight + 4 clamped corner
// indices + 4 premultiplied corner weights (0 if OOB). Phase 2 (256 thr = 4px x 8h x 8 lanes):
// each lane gathers uint2 (4 channels) per corner, branch-free.
__global__ __launch_bounds__(256)
void sample_kernel(const float* __restrict__ refp)
{
    __shared__ float s_w [4][NH_][8][4];
    __shared__ int   s_ix[4][NH_][8][4];

    const int blk = blockIdx.x;
    const int tid = threadIdx.x;

    {
        const int j   = tid & 7;          // point
        const int h   = (tid >> 3) & 7;   // head
        const int sub = tid >> 6;         // pixel within block
        const int pixel = blk * 4 + sub;
        const int b = pixel / (H_ * W_);
        const int rem = pixel - b * (H_ * W_);
        // torch .repeat quirk: ref for bh-index n = b*NH+h is ref_point[n % B]
        const int rb = (b * NH_ + h) % B_;
        const float ry = refp[(rb * (H_ * W_) + rem) * 2 + 0];
        const float rx = refp[(rb * (H_ * W_) + rem) * 2 + 1];

        const float lgj = g_offA[(size_t)pixel * NOAP + 128 + h * 8 + j];
        float mx = lgj;
#pragma unroll
        for (int o = 4; o; o >>= 1) mx = fmaxf(mx, __shfl_xor_sync(0xffffffffu, mx, o, 8));
        const float e = expf(lgj - mx);
        float s = e;
#pragma unroll
        for (int o = 4; o; o >>= 1) s += __shfl_xor_sync(0xffffffffu, s, o, 8);
        const float w = e / s;

        const float offy = g_offA[(size_t)pixel * NOAP + h * 16 + j * 2 + 0];
        const float offx = g_offA[(size_t)pixel * NOAP + h * 16 + j * 2 + 1];
        const float py = (ry + offy) * ((float)H_ / (float)(H_ - 1)) - 0.5f;
        const float px = (rx + offx) * ((float)W_ / (float)(W_ - 1)) - 0.5f;
        const float fy = floorf(py), fx = floorf(px);
        const int y0 = (int)fy, x0 = (int)fx;
        const float wy1 = py - fy, wx1 = px - fx;
        const float wy0 = 1.f - wy1, wx0 = 1.f - wx1;
        const bool yv0 = (y0 >= 0) && (y0 < H_);
        const bool yv1 = (y0 + 1 >= 0) && (y0 + 1 < H_);
        const bool xv0 = (x0 >= 0) && (x0 < W_);
        const bool xv1 = (x0 + 1 >= 0) && (x0 + 1 < W_);
        const int y0c = min(max(y0, 0), H_ - 1), y1c = min(max(y0 + 1, 0), H_ - 1);
        const int x0c = min(max(x0, 0), W_ - 1), x1c = min(max(x0 + 1, 0), W_ - 1);
        const int basepix = b * (H_ * W_);
        s_ix[sub][h][j][0] = (basepix + y0c * W_ + x0c) * DM_;
        s_ix[sub][h][j][1] = (basepix + y0c * W_ + x1c) * DM_;
        s_ix[sub][h][j][2] = (basepix + y1c * W_ + x0c) * DM_;
        s_ix[sub][h][j][3] = (basepix + y1c * W_ + x1c) * DM_;
        s_w [sub][h][j][0] = (yv0 && xv0) ? w * wy0 * wx0 : 0.f;
        s_w [sub][h][j][1] = (yv0 && xv1) ? w * wy0 * wx1 : 0.f;
        s_w [sub][h][j][2] = (yv1 && xv0) ? w * wy1 * wx0 : 0.f;
        s_w [sub][h][j][3] = (yv1 && xv1) ? w * wy1 * wx1 : 0.f;
    }
    __syncthreads();

    const int sub = tid >> 6;
    const int h = (tid >> 3) & 7;
    const int e = tid & 7;
    const int pixel = blk * 4 + sub;
    const int chan = h * 32 + e * 4;

    float a0 = 0.f, a1 = 0.f, a2 = 0.f, a3 = 0.f;
#pragma unroll
    for (int l = 0; l < 2; l++) {
        const __half* sf = (l ? g_sf1h : g_sf0h) + chan;
#pragma unroll
        for (int k = 0; k < 4; k++) {
            const int j = l * 4 + k;
            const float4 w4 = *(const float4*)(s_w[sub][h][j]);
            const int4   i4 = *(const int4*)(s_ix[sub][h][j]);
#pragma unroll
            for (int c = 0; c < 4; c++) {
                const int   idx = (&i4.x)[c];
                const float wc  = (&w4.x)[c];
                const uint2 u   = *(const uint2*)(sf + idx);
                const float2 p0 = __half22float2(*(const __half2*)(&u.x));
                const float2 p1 = __half22float2(*(const __half2*)(&u.y));
                a0 += wc * p0.x; a1 += wc * p0.y;
                a2 += wc * p1.x; a3 += wc * p1.y;
            }
        }
    }
    *(uint2*)(g_feath + (size_t)pixel * DM_ + chan) = make_uint2(pack2(a0, a1), pack2(a2, a3));
}

// ------------------------- launch -------------------------
extern "C" void kernel_launch(void* const* d_in, const int* in_sizes, int n_in,
                              void* d_out, int out_size)
{
    const float* query = (const float*)d_in[0];
    const float* keys0 = (const float*)d_in[1];
    const float* keys1 = (const float*)d_in[2];
    const float* refp  = (const float*)d_in[3];
    const float* Wq = (const float*)d_in[4];
    const float* bq = (const float*)d_in[5];
    const float* Wk = (const float*)d_in[6];
    const float* bk = (const float*)d_in[7];
    const float* Wo = (const float*)d_in[8];
    const float* bo = (const float*)d_in[9];
    const float* Wa = (const float*)d_in[10];
    const float* ba = (const float*)d_in[11];
    const float* Wm = (const float*)d_in[12];
    const float* bm = (const float*)d_in[13];
    float* out = (float*)d_out;

    __half *sf0h, *sf1h, *feath;
    float *offA, *Weff, *beff;
    cudaGetSymbolAddress((void**)&sf0h,  g_sf0h);
    cudaGetSymbolAddress((void**)&sf1h,  g_sf1h);
    cudaGetSymbolAddress((void**)&feath, g_feath);
    cudaGetSymbolAddress((void**)&offA,  g_offA);
    cudaGetSymbolAddress((void**)&Weff,  g_Weff);
    cudaGetSymbolAddress((void**)&beff,  g_beff);

    // >48KB dynamic smem needs opt-in (host-side attribute set; not a stream op)
    cudaFuncSetAttribute(gemm_heads, cudaFuncAttributeMaxDynamicSharedMemorySize, SMEM_BYTES);
    cudaFuncSetAttribute(gemm_out,   cudaFuncAttributeMaxDynamicSharedMemorySize, SMEM_BYTES);

    wbeff_kernel<<<DM_ + 1, 256>>>(Wq, Wo, Wa, bq, bo, ba);

    dim3 gh(NDIM / 128, NPIX / 128, 3);    // (2, 256, 3)
    gemm_heads<<<gh, 256, SMEM_BYTES>>>(query, Weff, beff, offA, keys0, keys1, Wk, bk, sf0h, sf1h);

    sample_kernel<<<NPIX / 4, 256>>>(refp);

    dim3 gg(NDIM / 128, NPIX / 128);       // (2, 256)
    gemm_out<<<gg, 256, SMEM_BYTES>>>(feath, Wm, bm, out);

    (void)in_sizes; (void)n_in; (void)out_size;
}